// round 3
// baseline (speedup 1.0000x reference)
#include <cuda_runtime.h>

#define B_   256
#define IN_  256
#define OUT_ 512
#define EPS_ 1e-7f

// Intermediate: rel_x[i][o]
__device__ float g_relx[IN_ * OUT_];

// ---------------------------------------------------------------------------
// Kernel 1: rel_x[i,o] = (sum_b min(t[b,o]/(x[b,i]+eps),1)) / (sum_b x[b,i])
// Fused: reciprocal computed inline at staging; colsum computed by warp 0
// with the exact sequential-b order. Tile 32i x 32o, 256 thr, 2x2/thread.
// Grid (8,16) = 128 blocks.
// ---------------------------------------------------------------------------
__global__ void k_relx(const float* __restrict__ x, const float* __restrict__ t) {
    __shared__ float Rs[128][32];
    __shared__ float Ts[128][32];
    __shared__ float s_cs[32];

    const int i0  = blockIdx.x * 32;
    const int o0  = blockIdx.y * 32;
    const int lid = threadIdx.x;
    const int tx  = lid & 15;   // i pair: 2tx, 2tx+1
    const int ty  = lid >> 4;   // o pair: 2ty, 2ty+1

    // Warp 0: colsum for this block's 32 i's (strictly sequential over b).
    if (lid < 32) {
        float s = 0.0f;
        #pragma unroll 16
        for (int b = 0; b < B_; b++) s += x[b * IN_ + i0 + lid];
        s_cs[lid] = s;
    }

    float acc00 = 0.f, acc01 = 0.f, acc10 = 0.f, acc11 = 0.f;

    for (int bb = 0; bb < B_; bb += 128) {
        #pragma unroll
        for (int k = 0; k < 4; k++) {
            int e   = lid + k * 256;      // 0..1023
            int row = e >> 3;             // 0..127
            int c4  = (e & 7) * 4;        // 0..28
            float4 xv = *(const float4*)&x[(bb + row) * IN_  + i0 + c4];
            float4 rv;
            rv.x = 1.0f / (xv.x + EPS_);
            rv.y = 1.0f / (xv.y + EPS_);
            rv.z = 1.0f / (xv.z + EPS_);
            rv.w = 1.0f / (xv.w + EPS_);
            *(float4*)&Rs[row][c4] = rv;
            *(float4*)&Ts[row][c4] = *(const float4*)&t[(bb + row) * OUT_ + o0 + c4];
        }
        __syncthreads();

        #pragma unroll 8
        for (int b = 0; b < 128; b++) {
            float2 r  = *(const float2*)&Rs[b][2 * tx];
            float2 tt = *(const float2*)&Ts[b][2 * ty];
            acc00 += fminf(tt.x * r.x, 1.0f);
            acc01 += fminf(tt.y * r.x, 1.0f);
            acc10 += fminf(tt.x * r.y, 1.0f);
            acc11 += fminf(tt.y * r.y, 1.0f);
        }
        __syncthreads();
    }

    const int i_0 = i0 + 2 * tx, i_1 = i_0 + 1;
    const int o_0 = o0 + 2 * ty, o_1 = o_0 + 1;
    float cs0 = s_cs[2 * tx];
    float cs1 = s_cs[2 * tx + 1];
    g_relx[i_0 * OUT_ + o_0] = acc00 / cs0;
    g_relx[i_0 * OUT_ + o_1] = acc01 / cs0;
    g_relx[i_1 * OUT_ + o_0] = acc10 / cs1;
    g_relx[i_1 * OUT_ + o_1] = acc11 / cs1;
}

// ---------------------------------------------------------------------------
// Kernel 2 (fused): per o-tile w-argmax + (b,o) argmax over i with fmax-only
// inner loop + chunk tracking + 32-wide rescan, writes outx & outw directly.
// Tile 32b x 32o, 256 thr, 2x2/thread. Grid (8,16) = 128 blocks.
// ---------------------------------------------------------------------------
__global__ void k_argmax(const float* __restrict__ x,
                         const float* __restrict__ w,
                         float* __restrict__ outx,
                         float* __restrict__ outw) {
    __shared__ float Xs[128][34];   // [i][b] transposed x half-tile
    __shared__ float Rl[128][32];   // [i][o] relx half-tile
    __shared__ int   s_iw[32];
    __shared__ float s_wv[32];

    const int b0  = blockIdx.x * 32;
    const int o0  = blockIdx.y * 32;
    const int lid = threadIdx.x;
    const int tb  = lid & 15;   // b pair: 2tb, 2tb+1
    const int to  = lid >> 4;   // o pair: 2to, 2to+1
    const int warp = lid >> 5;
    const int lane = lid & 31;

    // --- w-argmax for this block's 32 o's (each warp: 4 o's) ---
    #pragma unroll
    for (int k = 0; k < 4; k++) {
        int o = o0 + warp * 4 + k;
        float best = -1.f;
        int bi = 0;
        for (int i = lane; i < IN_; i += 32) {
            float v = w[i * OUT_ + o];
            if (v > best) { best = v; bi = i; }
        }
        #pragma unroll
        for (int off = 16; off > 0; off >>= 1) {
            float ov = __shfl_down_sync(0xffffffffu, best, off);
            int   oi = __shfl_down_sync(0xffffffffu, bi,   off);
            if (ov > best || (ov == best && oi < bi)) { best = ov; bi = oi; }
        }
        if (lane == 0) { s_iw[warp * 4 + k] = bi; s_wv[warp * 4 + k] = best; }
    }

    // --- main argmax: fmax-only inner loop, chunk-of-32 winner tracking ---
    float best00 = -1.f, best01 = -1.f, best10 = -1.f, best11 = -1.f;
    int   bc00 = 0, bc01 = 0, bc10 = 0, bc11 = 0;

    for (int half = 0; half < 2; half++) {
        const int iz = half * 128;
        // stage x (transposed) and relx for this half
        #pragma unroll
        for (int k = 0; k < 4; k++) {
            int e   = lid + k * 256;
            int row = e >> 5;                 // b-local 0..31
            int c4  = (e & 31) * 4;           // i-local 0..124
            float4 v = *(const float4*)&x[(b0 + row) * IN_ + iz + c4];
            Xs[c4 + 0][row] = v.x;
            Xs[c4 + 1][row] = v.y;
            Xs[c4 + 2][row] = v.z;
            Xs[c4 + 3][row] = v.w;
        }
        #pragma unroll
        for (int k = 0; k < 4; k++) {
            int e   = lid + k * 256;
            int row = e >> 3;                 // i-local 0..127
            int c4  = (e & 7) * 4;            // o-local
            *(float4*)&Rl[row][c4] = *(const float4*)&g_relx[(iz + row) * OUT_ + o0 + c4];
        }
        __syncthreads();

        #pragma unroll
        for (int c = 0; c < 4; c++) {         // chunks of 32 i within half
            float cm00 = -1.f, cm01 = -1.f, cm10 = -1.f, cm11 = -1.f;
            #pragma unroll 8
            for (int j = 0; j < 32; j++) {
                int i = c * 32 + j;
                float2 xv = *(const float2*)&Xs[i][2 * tb];
                float2 rv = *(const float2*)&Rl[i][2 * to];
                cm00 = fmaxf(cm00, xv.x * rv.x);
                cm01 = fmaxf(cm01, xv.x * rv.y);
                cm10 = fmaxf(cm10, xv.y * rv.x);
                cm11 = fmaxf(cm11, xv.y * rv.y);
            }
            const int cb = iz + c * 32;
            if (cm00 > best00) { best00 = cm00; bc00 = cb; }
            if (cm01 > best01) { best01 = cm01; bc01 = cb; }
            if (cm10 > best10) { best10 = cm10; bc10 = cb; }
            if (cm11 > best11) { best11 = cm11; bc11 = cb; }
        }
        __syncthreads();
    }

    // --- rescan winning chunk (descending j, overwrite on == -> first index) ---
    const int b_0 = b0 + 2 * tb, b_1 = b_0 + 1;
    const int o_0 = o0 + 2 * to, o_1 = o_0 + 1;

    int id00 = bc00, id01 = bc01, id10 = bc10, id11 = bc11;
    #pragma unroll 8
    for (int j = 31; j >= 0; j--) {
        float v;
        v = x[b_0 * IN_ + bc00 + j] * g_relx[(bc00 + j) * OUT_ + o_0];
        if (v == best00) id00 = bc00 + j;
        v = x[b_0 * IN_ + bc01 + j] * g_relx[(bc01 + j) * OUT_ + o_1];
        if (v == best01) id01 = bc01 + j;
        v = x[b_1 * IN_ + bc10 + j] * g_relx[(bc10 + j) * OUT_ + o_0];
        if (v == best10) id10 = bc10 + j;
        v = x[b_1 * IN_ + bc11 + j] * g_relx[(bc11 + j) * OUT_ + o_1];
        if (v == best11) id11 = bc11 + j;
    }

    // --- outputs ---
    outx[b_0 * OUT_ + o_0] = x[b_0 * IN_ + id00] * w[id00 * OUT_ + o_0];
    outx[b_0 * OUT_ + o_1] = x[b_0 * IN_ + id01] * w[id01 * OUT_ + o_1];
    outx[b_1 * OUT_ + o_0] = x[b_1 * IN_ + id10] * w[id10 * OUT_ + o_0];
    outx[b_1 * OUT_ + o_1] = x[b_1 * IN_ + id11] * w[id11 * OUT_ + o_1];

    const int iw0 = s_iw[2 * to],     iw1 = s_iw[2 * to + 1];
    const float wv0 = s_wv[2 * to],   wv1 = s_wv[2 * to + 1];
    outw[b_0 * OUT_ + o_0] = x[b_0 * IN_ + iw0] * wv0;
    outw[b_0 * OUT_ + o_1] = x[b_0 * IN_ + iw1] * wv1;
    outw[b_1 * OUT_ + o_0] = x[b_1 * IN_ + iw0] * wv0;
    outw[b_1 * OUT_ + o_1] = x[b_1 * IN_ + iw1] * wv1;
}

// ---------------------------------------------------------------------------
extern "C" void kernel_launch(void* const* d_in, const int* in_sizes, int n_in,
                              void* d_out, int out_size) {
    const float* x = (const float*)d_in[0];
    const float* w = (const float*)d_in[1];
    const float* t = (const float*)d_in[2];
    float* outx = (float*)d_out;
    float* outw = (float*)d_out + B_ * OUT_;

    k_relx  <<<dim3(IN_ / 32, OUT_ / 32), 256>>>(x, t);
    k_argmax<<<dim3(B_  / 32, OUT_ / 32), 256>>>(x, w, outx, outw);
}

// round 4
// speedup vs baseline: 1.3070x; 1.3070x over previous
#include <cuda_runtime.h>

#define B_   256
#define IN_  256
#define OUT_ 512
#define EPS_ 1e-7f

__device__ float g_relx[IN_ * OUT_];   // rel_x[i][o]
__device__ float g_colsum[IN_];        // sum_b x[b,i], sequential-b order
__device__ int   g_iw[OUT_];           // argmax_i w[i,o]
__device__ float g_wv[OUT_];           // w[iw,o]

// ---------------------------------------------------------------------------
// Kernel 0: block 0 -> colsum (one thread per i, strictly sequential over b);
//           blocks 1..2 -> w-argmax, one thread per o, coalesced over o.
// ---------------------------------------------------------------------------
__global__ void kInit(const float* __restrict__ x, const float* __restrict__ w) {
    const int tid = threadIdx.x;
    if (blockIdx.x == 0) {
        float s = 0.0f;
        #pragma unroll 16
        for (int b = 0; b < B_; b++) s += x[b * IN_ + tid];
        g_colsum[tid] = s;
        return;
    }
    // thread-per-o argmax over i (v > best keeps first index). Coalesced LDG.
    const int o = (blockIdx.x - 1) * 256 + tid;
    float best = -1.f;
    int bi = 0;
    #pragma unroll 8
    for (int i = 0; i < IN_; i++) {
        float v = w[i * OUT_ + o];
        if (v > best) { best = v; bi = i; }
    }
    g_iw[o] = bi;
    g_wv[o] = best;
}

// ---------------------------------------------------------------------------
// Kernel 1: rel_x[i,o] = (sum_b min(t[b,o]/(x[b,i]+eps),1)) / colsum[i]
// Tile 32i x 16o, 256 thr (o fastest), 2i x 1o per thread. Grid (8,32)=256.
// Reciprocal inline at staging; b staged in 2 chunks of 128 (ascending order).
// ---------------------------------------------------------------------------
__global__ void k_relx(const float* __restrict__ x, const float* __restrict__ t) {
    __shared__ float Rs[128][32];   // [b][i_local] reciprocals
    __shared__ float Ts[128][16];   // [b][o_local]

    const int i0  = blockIdx.x * 32;
    const int o0  = blockIdx.y * 16;
    const int lid = threadIdx.x;
    const int to  = lid & 15;    // o
    const int tp  = lid >> 4;    // i pair: 2tp, 2tp+1

    float acc0 = 0.f, acc1 = 0.f;

    for (int bb = 0; bb < B_; bb += 128) {
        #pragma unroll
        for (int k = 0; k < 4; k++) {       // Rs: 4096 floats
            int e   = lid + k * 256;
            int row = e >> 3;
            int c4  = (e & 7) * 4;
            float4 xv = *(const float4*)&x[(bb + row) * IN_ + i0 + c4];
            float4 rv;
            rv.x = 1.0f / (xv.x + EPS_);
            rv.y = 1.0f / (xv.y + EPS_);
            rv.z = 1.0f / (xv.z + EPS_);
            rv.w = 1.0f / (xv.w + EPS_);
            *(float4*)&Rs[row][c4] = rv;
        }
        #pragma unroll
        for (int k = 0; k < 2; k++) {       // Ts: 2048 floats
            int e   = lid + k * 256;
            int row = e >> 2;
            int c4  = (e & 3) * 4;
            *(float4*)&Ts[row][c4] = *(const float4*)&t[(bb + row) * OUT_ + o0 + c4];
        }
        __syncthreads();

        #pragma unroll 8
        for (int b = 0; b < 128; b++) {
            float2 r  = *(const float2*)&Rs[b][2 * tp];
            float  tv = Ts[b][to];
            acc0 += fminf(tv * r.x, 1.0f);
            acc1 += fminf(tv * r.y, 1.0f);
        }
        __syncthreads();
    }

    const int i_0 = i0 + 2 * tp, i_1 = i_0 + 1;
    const int o   = o0 + to;
    g_relx[i_0 * OUT_ + o] = acc0 / g_colsum[i_0];
    g_relx[i_1 * OUT_ + o] = acc1 / g_colsum[i_1];
}

// ---------------------------------------------------------------------------
// Kernel 2 (fused): argmax_i x[b,i]*relx[i,o] (predicated first-max tracking)
// + direct output of chosen_x and chosen_w.
// Tile 16b x 32o, 256 thr (o fastest), 1b x 2o per thread. Grid (16,16)=256.
// ---------------------------------------------------------------------------
__global__ void k_argmax(const float* __restrict__ x,
                         const float* __restrict__ w,
                         float* __restrict__ outx,
                         float* __restrict__ outw) {
    __shared__ float Xs[128][17];   // [i][b_local] transposed x half-tile
    __shared__ float Rl[128][32];   // [i][o_local] relx half-tile

    const int b0  = blockIdx.x * 16;
    const int o0  = blockIdx.y * 32;
    const int lid = threadIdx.x;
    const int to  = lid & 15;    // o pair: 2to, 2to+1
    const int tb  = lid >> 4;    // b: 0..15

    float best0 = -1.f, best1 = -1.f;
    int   id0 = 0, id1 = 0;

    for (int half = 0; half < 2; half++) {
        const int iz = half * 128;
        #pragma unroll
        for (int k = 0; k < 2; k++) {       // Xs: 2048 floats (transposed)
            int e   = lid + k * 256;
            int row = e >> 5;               // b-local 0..15
            int c4  = (e & 31) * 4;         // i-local
            float4 v = *(const float4*)&x[(b0 + row) * IN_ + iz + c4];
            Xs[c4 + 0][row] = v.x;
            Xs[c4 + 1][row] = v.y;
            Xs[c4 + 2][row] = v.z;
            Xs[c4 + 3][row] = v.w;
        }
        #pragma unroll
        for (int k = 0; k < 4; k++) {       // Rl: 4096 floats
            int e   = lid + k * 256;
            int row = e >> 3;
            int c4  = (e & 7) * 4;
            *(float4*)&Rl[row][c4] = *(const float4*)&g_relx[(iz + row) * OUT_ + o0 + c4];
        }
        __syncthreads();

        #pragma unroll 16
        for (int i = 0; i < 128; i++) {
            const int gi = iz + i;
            float  xv = Xs[i][tb];
            float2 rv = *(const float2*)&Rl[i][2 * to];
            float v0 = xv * rv.x;
            float v1 = xv * rv.y;
            if (v0 > best0) { best0 = v0; id0 = gi; }
            if (v1 > best1) { best1 = v1; id1 = gi; }
        }
        __syncthreads();
    }

    const int b  = b0 + tb;
    const int o_ = o0 + 2 * to;

    float2 ox;
    ox.x = x[b * IN_ + id0] * w[id0 * OUT_ + o_];
    ox.y = x[b * IN_ + id1] * w[id1 * OUT_ + o_ + 1];
    *(float2*)&outx[b * OUT_ + o_] = ox;

    int   iw0 = g_iw[o_],  iw1 = g_iw[o_ + 1];
    float wv0 = g_wv[o_],  wv1 = g_wv[o_ + 1];
    float2 ow;
    ow.x = x[b * IN_ + iw0] * wv0;
    ow.y = x[b * IN_ + iw1] * wv1;
    *(float2*)&outw[b * OUT_ + o_] = ow;
}

// ---------------------------------------------------------------------------
extern "C" void kernel_launch(void* const* d_in, const int* in_sizes, int n_in,
                              void* d_out, int out_size) {
    const float* x = (const float*)d_in[0];
    const float* w = (const float*)d_in[1];
    const float* t = (const float*)d_in[2];
    float* outx = (float*)d_out;
    float* outw = (float*)d_out + B_ * OUT_;

    kInit   <<<3, 256>>>(x, w);
    k_relx  <<<dim3(IN_ / 32, OUT_ / 16), 256>>>(x, t);
    k_argmax<<<dim3(B_  / 16, OUT_ / 32), 256>>>(x, w, outx, outw);
}

// round 5
// speedup vs baseline: 1.4907x; 1.1405x over previous
#include <cuda_runtime.h>

#define B_   256
#define IN_  256
#define OUT_ 512
#define EPS_ 1e-7f

__device__ float g_relx[IN_ * OUT_];   // rel_x[i][o]
__device__ float g_colsum[IN_];        // sum_b x[b,i], sequential-b order
__device__ int   g_iw[OUT_];           // argmax_i w[i,o]
__device__ float g_wv[OUT_];           // w[iw,o]

// ---------------------------------------------------------------------------
// Kernel 0: block 0 -> colsum (thread per i, strictly sequential over b, but
//           loads batched 32-wide for MLP); blocks 1..16 -> w-argmax, each
//           block 32 o's, 8 i-chunks x 32 lanes, exact first-max chunk merge.
// ---------------------------------------------------------------------------
__global__ void kInit(const float* __restrict__ x, const float* __restrict__ w) {
    const int tid = threadIdx.x;

    if (blockIdx.x == 0) {
        // colsum: batch loads (independent) then add in strict ascending-b order
        float s = 0.0f;
        #pragma unroll
        for (int c = 0; c < 8; c++) {
            float v[32];
            #pragma unroll
            for (int j = 0; j < 32; j++)
                v[j] = x[(c * 32 + j) * IN_ + tid];
            #pragma unroll
            for (int j = 0; j < 32; j++)
                s += v[j];
        }
        g_colsum[tid] = s;
        return;
    }

    // w-argmax: block handles 32 o's; thread (ic, ol) scans i in [ic*32, ic*32+32)
    __shared__ float sv[8][32];
    __shared__ int   si[8][32];

    const int blk = blockIdx.x - 1;      // 0..15
    const int ol  = tid & 31;            // o lane
    const int ic  = tid >> 5;            // i-chunk 0..7
    const int o   = blk * 32 + ol;

    float best = -1.f;
    int   bi   = 0;
    #pragma unroll
    for (int j = 0; j < 32; j++) {
        int i = ic * 32 + j;
        float v = w[i * OUT_ + o];
        if (v > best) { best = v; bi = i; }
    }
    sv[ic][ol] = best;
    si[ic][ol] = bi;
    __syncthreads();

    if (tid < 32) {
        float b  = sv[0][tid];
        int   ix = si[0][tid];
        #pragma unroll
        for (int c = 1; c < 8; c++) {
            if (sv[c][tid] > b) { b = sv[c][tid]; ix = si[c][tid]; }
        }
        g_iw[blk * 32 + tid] = ix;
        g_wv[blk * 32 + tid] = b;
    }
}

// ---------------------------------------------------------------------------
// Kernel 1: rel_x[i,o] = (sum_b min(t[b,o]/(x[b,i]+eps),1)) / colsum[i]
// Tile 32i x 16o, 256 thr (o fastest), 2i x 1o per thread. Grid (8,32)=256.
// ---------------------------------------------------------------------------
__global__ void k_relx(const float* __restrict__ x, const float* __restrict__ t) {
    __shared__ float Rs[128][32];   // [b][i_local] reciprocals
    __shared__ float Ts[128][16];   // [b][o_local]

    const int i0  = blockIdx.x * 32;
    const int o0  = blockIdx.y * 16;
    const int lid = threadIdx.x;
    const int to  = lid & 15;    // o
    const int tp  = lid >> 4;    // i pair: 2tp, 2tp+1

    float acc0 = 0.f, acc1 = 0.f;

    for (int bb = 0; bb < B_; bb += 128) {
        #pragma unroll
        for (int k = 0; k < 4; k++) {       // Rs: 4096 floats
            int e   = lid + k * 256;
            int row = e >> 3;
            int c4  = (e & 7) * 4;
            float4 xv = *(const float4*)&x[(bb + row) * IN_ + i0 + c4];
            float4 rv;
            rv.x = 1.0f / (xv.x + EPS_);
            rv.y = 1.0f / (xv.y + EPS_);
            rv.z = 1.0f / (xv.z + EPS_);
            rv.w = 1.0f / (xv.w + EPS_);
            *(float4*)&Rs[row][c4] = rv;
        }
        #pragma unroll
        for (int k = 0; k < 2; k++) {       // Ts: 2048 floats
            int e   = lid + k * 256;
            int row = e >> 2;
            int c4  = (e & 3) * 4;
            *(float4*)&Ts[row][c4] = *(const float4*)&t[(bb + row) * OUT_ + o0 + c4];
        }
        __syncthreads();

        #pragma unroll 8
        for (int b = 0; b < 128; b++) {
            float2 r  = *(const float2*)&Rs[b][2 * tp];
            float  tv = Ts[b][to];
            acc0 += fminf(tv * r.x, 1.0f);
            acc1 += fminf(tv * r.y, 1.0f);
        }
        __syncthreads();
    }

    const int i_0 = i0 + 2 * tp, i_1 = i_0 + 1;
    const int o   = o0 + to;
    g_relx[i_0 * OUT_ + o] = acc0 / g_colsum[i_0];
    g_relx[i_1 * OUT_ + o] = acc1 / g_colsum[i_1];
}

// ---------------------------------------------------------------------------
// Kernel 2 (fused): argmax_i x[b,i]*relx[i,o] (predicated first-max tracking)
// + direct output of chosen_x and chosen_w.
// Tile 16b x 32o, 256 thr (o fastest), 1b x 2o per thread. Grid (16,16)=256.
// ---------------------------------------------------------------------------
__global__ void k_argmax(const float* __restrict__ x,
                         const float* __restrict__ w,
                         float* __restrict__ outx,
                         float* __restrict__ outw) {
    __shared__ float Xs[128][17];   // [i][b_local] transposed x half-tile
    __shared__ float Rl[128][32];   // [i][o_local] relx half-tile

    const int b0  = blockIdx.x * 16;
    const int o0  = blockIdx.y * 32;
    const int lid = threadIdx.x;
    const int to  = lid & 15;    // o pair: 2to, 2to+1
    const int tb  = lid >> 4;    // b: 0..15

    float best0 = -1.f, best1 = -1.f;
    int   id0 = 0, id1 = 0;

    for (int half = 0; half < 2; half++) {
        const int iz = half * 128;
        #pragma unroll
        for (int k = 0; k < 2; k++) {       // Xs: 2048 floats (transposed)
            int e   = lid + k * 256;
            int row = e >> 5;               // b-local 0..15
            int c4  = (e & 31) * 4;         // i-local
            float4 v = *(const float4*)&x[(b0 + row) * IN_ + iz + c4];
            Xs[c4 + 0][row] = v.x;
            Xs[c4 + 1][row] = v.y;
            Xs[c4 + 2][row] = v.z;
            Xs[c4 + 3][row] = v.w;
        }
        #pragma unroll
        for (int k = 0; k < 4; k++) {       // Rl: 4096 floats
            int e   = lid + k * 256;
            int row = e >> 3;
            int c4  = (e & 7) * 4;
            *(float4*)&Rl[row][c4] = *(const float4*)&g_relx[(iz + row) * OUT_ + o0 + c4];
        }
        __syncthreads();

        #pragma unroll 16
        for (int i = 0; i < 128; i++) {
            const int gi = iz + i;
            float  xv = Xs[i][tb];
            float2 rv = *(const float2*)&Rl[i][2 * to];
            float v0 = xv * rv.x;
            float v1 = xv * rv.y;
            if (v0 > best0) { best0 = v0; id0 = gi; }
            if (v1 > best1) { best1 = v1; id1 = gi; }
        }
        __syncthreads();
    }

    const int b  = b0 + tb;
    const int o_ = o0 + 2 * to;

    float2 ox;
    ox.x = x[b * IN_ + id0] * w[id0 * OUT_ + o_];
    ox.y = x[b * IN_ + id1] * w[id1 * OUT_ + o_ + 1];
    *(float2*)&outx[b * OUT_ + o_] = ox;

    int   iw0 = g_iw[o_],  iw1 = g_iw[o_ + 1];
    float wv0 = g_wv[o_],  wv1 = g_wv[o_ + 1];
    float2 ow;
    ow.x = x[b * IN_ + iw0] * wv0;
    ow.y = x[b * IN_ + iw1] * wv1;
    *(float2*)&outw[b * OUT_ + o_] = ow;
}

// ---------------------------------------------------------------------------
extern "C" void kernel_launch(void* const* d_in, const int* in_sizes, int n_in,
                              void* d_out, int out_size) {
    const float* x = (const float*)d_in[0];
    const float* w = (const float*)d_in[1];
    const float* t = (const float*)d_in[2];
    float* outx = (float*)d_out;
    float* outw = (float*)d_out + B_ * OUT_;

    kInit   <<<17, 256>>>(x, w);
    k_relx  <<<dim3(IN_ / 32, OUT_ / 16), 256>>>(x, t);
    k_argmax<<<dim3(B_  / 16, OUT_ / 32), 256>>>(x, w, outx, outw);
}